// round 1
// baseline (speedup 1.0000x reference)
#include <cuda_runtime.h>
#include <math.h>

#define BSZ    2048
#define LATENT 128
#define CCLS   8
#define HID    1024
#define DD     512
#define NMAXX  4096

#define BM 128
#define BN 128
#define BK 8
#define TM 8
#define TN 8
#define NTHREADS 256

__constant__ int c_counts[CCLS] = {1024, 1536, 2048, 2560, 3072, 3584, 3840, 4096};

// Scratch (device globals: allocation-free per harness rules)
__device__ float g_h[BSZ * HID];
__device__ float g_t[BSZ * HID];
__device__ float g_logits[(size_t)BSZ * NMAXX];
__device__ int   g_order[BSZ];
__device__ int   g_class_off[CCLS + 1];

__device__ __forceinline__ float gelu_exact(float x) {
    return 0.5f * x * (1.0f + erff(x * 0.70710678118654752f));
}

// ---------------------------------------------------------------------------
// Group samples by class: g_order[slot] = b, g_class_off prefix offsets.
// ---------------------------------------------------------------------------
__global__ void group_kernel(const int* __restrict__ cls) {
    __shared__ int cnt[CCLS];
    __shared__ int off[CCLS + 1];
    int tid = threadIdx.x;
    if (tid < CCLS) cnt[tid] = 0;
    __syncthreads();
    for (int b = tid; b < BSZ; b += blockDim.x) atomicAdd(&cnt[cls[b]], 1);
    __syncthreads();
    if (tid == 0) {
        int s = 0;
        for (int c = 0; c < CCLS; c++) { off[c] = s; s += cnt[c]; }
        off[CCLS] = s;
        for (int c = 0; c <= CCLS; c++) g_class_off[c] = off[c];
    }
    __syncthreads();
    if (tid < CCLS) cnt[tid] = off[tid];  // cursors
    __syncthreads();
    for (int b = tid; b < BSZ; b += blockDim.x) {
        int c = cls[b];
        int slot = atomicAdd(&cnt[c], 1);
        g_order[slot] = b;
    }
}

// ---------------------------------------------------------------------------
// Kernel 1: h = gelu(z @ W1[:128] + W1[128+cid] + b1)    M=2048 K=128 N=1024
// ---------------------------------------------------------------------------
__global__ __launch_bounds__(NTHREADS) void k_gemm_h(
    const float* __restrict__ z, const int* __restrict__ cls,
    const float* __restrict__ W1, const float* __restrict__ b1) {
    __shared__ float As[BK][BM];
    __shared__ float Bs[BK][BN];
    int tid = threadIdx.x;
    int tx = tid & 15, ty = tid >> 4;
    int m0 = blockIdx.y * BM;
    int n0 = blockIdx.x * BN;
    float acc[TM][TN] = {};
    int la_m = tid >> 1;
    int la_k = (tid & 1) * 4;
    int lb_k = tid >> 5;
    int lb_n = (tid & 31) * 4;

    for (int k0 = 0; k0 < LATENT; k0 += BK) {
        float4 a4 = *(const float4*)(z + (size_t)(m0 + la_m) * LATENT + k0 + la_k);
        As[la_k + 0][la_m] = a4.x; As[la_k + 1][la_m] = a4.y;
        As[la_k + 2][la_m] = a4.z; As[la_k + 3][la_m] = a4.w;
        *(float4*)&Bs[lb_k][lb_n] =
            *(const float4*)(W1 + (size_t)(k0 + lb_k) * HID + n0 + lb_n);
        __syncthreads();
#pragma unroll
        for (int k = 0; k < BK; ++k) {
            float ra[TM], rb[TN];
            *(float4*)&ra[0] = *(const float4*)&As[k][ty * TM];
            *(float4*)&ra[4] = *(const float4*)&As[k][ty * TM + 4];
            *(float4*)&rb[0] = *(const float4*)&Bs[k][tx * TN];
            *(float4*)&rb[4] = *(const float4*)&Bs[k][tx * TN + 4];
#pragma unroll
            for (int i = 0; i < TM; i++)
#pragma unroll
                for (int j = 0; j < TN; j++) acc[i][j] += ra[i] * rb[j];
        }
        __syncthreads();
    }
#pragma unroll
    for (int i = 0; i < TM; i++) {
        int m = m0 + ty * TM + i;
        int cid = cls[m];
        const float* wrow = W1 + (size_t)(LATENT + cid) * HID;
#pragma unroll
        for (int j = 0; j < TN; j++) {
            int n = n0 + tx * TN + j;
            g_h[(size_t)m * HID + n] = gelu_exact(acc[i][j] + wrow[n] + b1[n]);
        }
    }
}

// ---------------------------------------------------------------------------
// Kernel 2: t = gelu(h @ W2 + b2)    M=2048 K=1024 N=1024
// ---------------------------------------------------------------------------
__global__ __launch_bounds__(NTHREADS) void k_gemm_t(
    const float* __restrict__ W2, const float* __restrict__ b2) {
    __shared__ float As[BK][BM];
    __shared__ float Bs[BK][BN];
    int tid = threadIdx.x;
    int tx = tid & 15, ty = tid >> 4;
    int m0 = blockIdx.y * BM;
    int n0 = blockIdx.x * BN;
    float acc[TM][TN] = {};
    int la_m = tid >> 1;
    int la_k = (tid & 1) * 4;
    int lb_k = tid >> 5;
    int lb_n = (tid & 31) * 4;

    for (int k0 = 0; k0 < HID; k0 += BK) {
        float4 a4 = *(const float4*)(g_h + (size_t)(m0 + la_m) * HID + k0 + la_k);
        As[la_k + 0][la_m] = a4.x; As[la_k + 1][la_m] = a4.y;
        As[la_k + 2][la_m] = a4.z; As[la_k + 3][la_m] = a4.w;
        *(float4*)&Bs[lb_k][lb_n] =
            *(const float4*)(W2 + (size_t)(k0 + lb_k) * HID + n0 + lb_n);
        __syncthreads();
#pragma unroll
        for (int k = 0; k < BK; ++k) {
            float ra[TM], rb[TN];
            *(float4*)&ra[0] = *(const float4*)&As[k][ty * TM];
            *(float4*)&ra[4] = *(const float4*)&As[k][ty * TM + 4];
            *(float4*)&rb[0] = *(const float4*)&Bs[k][tx * TN];
            *(float4*)&rb[4] = *(const float4*)&Bs[k][tx * TN + 4];
#pragma unroll
            for (int i = 0; i < TM; i++)
#pragma unroll
                for (int j = 0; j < TN; j++) acc[i][j] += ra[i] * rb[j];
        }
        __syncthreads();
    }
#pragma unroll
    for (int i = 0; i < TM; i++) {
        int m = m0 + ty * TM + i;
#pragma unroll
        for (int j = 0; j < TN; j++) {
            int n = n0 + tx * TN + j;
            g_t[(size_t)m * HID + n] = gelu_exact(acc[i][j] + b2[n]);
        }
    }
}

// ---------------------------------------------------------------------------
// Kernel 3: grouped logits GEMM: logits[r,n] = t[order[r]] . Wa[c][:,n] + ba
//   grid (NMAXX/BN, 16, CCLS); dead tiles exit early.
// ---------------------------------------------------------------------------
__global__ __launch_bounds__(NTHREADS) void k_logits(
    const float* __restrict__ Wa, const float* __restrict__ ba) {
    int c = blockIdx.z;
    int off = g_class_off[c];
    int Bc = g_class_off[c + 1] - off;
    int mt = blockIdx.y, nt = blockIdx.x;
    if (mt * BM >= Bc) return;
    int cnt = c_counts[c];
    if (nt * BN >= cnt) return;

    __shared__ float As[BK][BM];
    __shared__ float Bs[BK][BN];
    int tid = threadIdx.x;
    int tx = tid & 15, ty = tid >> 4;
    int n0 = nt * BN;
    float acc[TM][TN] = {};
    int la_m = tid >> 1;
    int la_k = (tid & 1) * 4;
    int lb_k = tid >> 5;
    int lb_n = (tid & 31) * 4;

    int gml = mt * BM + la_m;
    const float* Arow = (gml < Bc) ? (g_t + (size_t)g_order[off + gml] * HID) : 0;
    const float* Bbase = Wa + (size_t)c * HID * NMAXX;

    for (int k0 = 0; k0 < HID; k0 += BK) {
        float4 a4 = make_float4(0.f, 0.f, 0.f, 0.f);
        if (Arow) a4 = *(const float4*)(Arow + k0 + la_k);
        As[la_k + 0][la_m] = a4.x; As[la_k + 1][la_m] = a4.y;
        As[la_k + 2][la_m] = a4.z; As[la_k + 3][la_m] = a4.w;
        *(float4*)&Bs[lb_k][lb_n] =
            *(const float4*)(Bbase + (size_t)(k0 + lb_k) * NMAXX + n0 + lb_n);
        __syncthreads();
#pragma unroll
        for (int k = 0; k < BK; ++k) {
            float ra[TM], rb[TN];
            *(float4*)&ra[0] = *(const float4*)&As[k][ty * TM];
            *(float4*)&ra[4] = *(const float4*)&As[k][ty * TM + 4];
            *(float4*)&rb[0] = *(const float4*)&Bs[k][tx * TN];
            *(float4*)&rb[4] = *(const float4*)&Bs[k][tx * TN + 4];
#pragma unroll
            for (int i = 0; i < TM; i++)
#pragma unroll
                for (int j = 0; j < TN; j++) acc[i][j] += ra[i] * rb[j];
        }
        __syncthreads();
    }
#pragma unroll
    for (int i = 0; i < TM; i++) {
        int ml = mt * BM + ty * TM + i;
        if (ml < Bc) {
            size_t r = off + ml;
#pragma unroll
            for (int j = 0; j < TN; j++) {
                int n = n0 + tx * TN + j;
                g_logits[r * NMAXX + n] = acc[i][j] + ba[(size_t)c * NMAXX + n];
            }
        }
    }
}

// ---------------------------------------------------------------------------
// Kernel 4: softmax in-place over valid prefix of each logits row.
// ---------------------------------------------------------------------------
__global__ __launch_bounds__(NTHREADS) void k_softmax() {
    int r = blockIdx.x;
    int c = 0;
#pragma unroll
    for (int i = 1; i < CCLS; i++)
        if (r >= g_class_off[i]) c = i;
    int cnt = c_counts[c];
    float* row = g_logits + (size_t)r * NMAXX;
    int tid = threadIdx.x;
    __shared__ float red[NTHREADS];

    float mx = -1e30f;
    for (int i = tid * 4; i < cnt; i += NTHREADS * 4) {
        float4 v = *(const float4*)(row + i);
        mx = fmaxf(mx, fmaxf(fmaxf(v.x, v.y), fmaxf(v.z, v.w)));
    }
    red[tid] = mx;
    __syncthreads();
    for (int s = NTHREADS / 2; s > 0; s >>= 1) {
        if (tid < s) red[tid] = fmaxf(red[tid], red[tid + s]);
        __syncthreads();
    }
    mx = red[0];
    __syncthreads();

    float sum = 0.f;
    for (int i = tid * 4; i < cnt; i += NTHREADS * 4) {
        float4 v = *(const float4*)(row + i);
        v.x = __expf(v.x - mx); v.y = __expf(v.y - mx);
        v.z = __expf(v.z - mx); v.w = __expf(v.w - mx);
        sum += v.x + v.y + v.z + v.w;
        *(float4*)(row + i) = v;
    }
    red[tid] = sum;
    __syncthreads();
    for (int s = NTHREADS / 2; s > 0; s >>= 1) {
        if (tid < s) red[tid] += red[tid + s];
        __syncthreads();
    }
    float inv = 1.0f / red[0];
    __syncthreads();

    for (int i = tid * 4; i < cnt; i += NTHREADS * 4) {
        float4 v = *(const float4*)(row + i);
        v.x *= inv; v.y *= inv; v.z *= inv; v.w *= inv;
        *(float4*)(row + i) = v;
    }
}

// ---------------------------------------------------------------------------
// Kernel 5: grouped output GEMM: out[order[r]] = alpha[r,:cnt] @ Xbuf[c][:cnt]
//   M=Bc, K=cnt, N=512.  grid (DD/BN, 16, CCLS)
// ---------------------------------------------------------------------------
__global__ __launch_bounds__(NTHREADS) void k_out(
    const float* __restrict__ Xbuf, float* __restrict__ out) {
    int c = blockIdx.z;
    int off = g_class_off[c];
    int Bc = g_class_off[c + 1] - off;
    int mt = blockIdx.y, nt = blockIdx.x;
    if (mt * BM >= Bc) return;
    int cnt = c_counts[c];

    __shared__ float As[BK][BM];
    __shared__ float Bs[BK][BN];
    int tid = threadIdx.x;
    int tx = tid & 15, ty = tid >> 4;
    int n0 = nt * BN;
    float acc[TM][TN] = {};
    int la_m = tid >> 1;
    int la_k = (tid & 1) * 4;
    int lb_k = tid >> 5;
    int lb_n = (tid & 31) * 4;

    int gml = mt * BM + la_m;
    const float* Arow = (gml < Bc) ? (g_logits + (size_t)(off + gml) * NMAXX) : 0;
    const float* Bbase = Xbuf + (size_t)c * NMAXX * DD;

    for (int k0 = 0; k0 < cnt; k0 += BK) {
        float4 a4 = make_float4(0.f, 0.f, 0.f, 0.f);
        if (Arow) a4 = *(const float4*)(Arow + k0 + la_k);
        As[la_k + 0][la_m] = a4.x; As[la_k + 1][la_m] = a4.y;
        As[la_k + 2][la_m] = a4.z; As[la_k + 3][la_m] = a4.w;
        *(float4*)&Bs[lb_k][lb_n] =
            *(const float4*)(Bbase + (size_t)(k0 + lb_k) * DD + n0 + lb_n);
        __syncthreads();
#pragma unroll
        for (int k = 0; k < BK; ++k) {
            float ra[TM], rb[TN];
            *(float4*)&ra[0] = *(const float4*)&As[k][ty * TM];
            *(float4*)&ra[4] = *(const float4*)&As[k][ty * TM + 4];
            *(float4*)&rb[0] = *(const float4*)&Bs[k][tx * TN];
            *(float4*)&rb[4] = *(const float4*)&Bs[k][tx * TN + 4];
#pragma unroll
            for (int i = 0; i < TM; i++)
#pragma unroll
                for (int j = 0; j < TN; j++) acc[i][j] += ra[i] * rb[j];
        }
        __syncthreads();
    }
#pragma unroll
    for (int i = 0; i < TM; i++) {
        int ml = mt * BM + ty * TM + i;
        if (ml < Bc) {
            int b = g_order[off + ml];
#pragma unroll
            for (int j = 0; j < TN; j++) {
                int n = n0 + tx * TN + j;
                out[(size_t)b * DD + n] = acc[i][j];
            }
        }
    }
}

// ---------------------------------------------------------------------------
extern "C" void kernel_launch(void* const* d_in, const int* in_sizes, int n_in,
                              void* d_out, int out_size) {
    const float* z   = (const float*)d_in[0];
    const int*   cls = (const int*)d_in[1];
    const float* W1  = (const float*)d_in[2];
    const float* b1  = (const float*)d_in[3];
    const float* W2  = (const float*)d_in[4];
    const float* b2  = (const float*)d_in[5];
    const float* Wa  = (const float*)d_in[6];
    const float* ba  = (const float*)d_in[7];
    const float* Xb  = (const float*)d_in[8];
    float* out = (float*)d_out;

    group_kernel<<<1, NTHREADS>>>(cls);
    k_gemm_h<<<dim3(HID / BN, BSZ / BM), NTHREADS>>>(z, cls, W1, b1);
    k_gemm_t<<<dim3(HID / BN, BSZ / BM), NTHREADS>>>(W2, b2);
    k_logits<<<dim3(NMAXX / BN, BSZ / BM, CCLS), NTHREADS>>>(Wa, ba);
    k_softmax<<<BSZ, NTHREADS>>>();
    k_out<<<dim3(DD / BN, BSZ / BM, CCLS), NTHREADS>>>(Xb, out);
}

// round 2
// speedup vs baseline: 2.9184x; 2.9184x over previous
#include <cuda_runtime.h>
#include <math.h>
#include <stdint.h>

#define BSZ    2048
#define LATENT 128
#define CCLS   8
#define HID    1024
#define DD     512
#define NMAXX  4096
#define NT     256

__constant__ int c_counts[CCLS] = {1024, 1536, 2048, 2560, 3072, 3584, 3840, 4096};

// Scratch (device globals: allocation-free per harness rules)
__device__ __align__(16) float g_h[BSZ * HID];
__device__ __align__(16) float g_t[BSZ * HID];
__device__ __align__(16) float g_logits[(size_t)BSZ * NMAXX];
__device__ __align__(16) float g_colmean[CCLS * DD];
__device__ int g_order[BSZ];
__device__ int g_class_off[CCLS + 1];

__device__ __forceinline__ float gelu_exact(float x) {
    return 0.5f * x * (1.0f + erff(x * 0.70710678118654752f));
}
__device__ __forceinline__ uint32_t f2b(float f) { return __float_as_uint(f); }

// tf32 mma: D(16x8) += A(16x8) * B(8x8), fp32 accumulate
__device__ __forceinline__ void mma8(float* d, const uint32_t* a, const uint32_t* b) {
    asm volatile(
        "mma.sync.aligned.m16n8k8.row.col.f32.tf32.tf32.f32 "
        "{%0,%1,%2,%3},{%4,%5,%6,%7},{%8,%9},{%0,%1,%2,%3};\n"
        : "+f"(d[0]), "+f"(d[1]), "+f"(d[2]), "+f"(d[3])
        : "r"(a[0]), "r"(a[1]), "r"(a[2]), "r"(a[3]), "r"(b[0]), "r"(b[1]));
}

__device__ __forceinline__ void cpa16(uint32_t dst, const float* src, bool pred) {
    int sz = pred ? 16 : 0;
    asm volatile("cp.async.ca.shared.global [%0], [%1], 16, %2;\n"
                 :: "r"(dst), "l"(src), "r"(sz));
}
#define CP_COMMIT asm volatile("cp.async.commit_group;\n")
#define CP_WAIT1  asm volatile("cp.async.wait_group 1;\n")

#define ASTR 20     // A smem stride (words): bank-conflict-free fragment loads
#define BSTR 136    // B smem stride (words): 136 % 32 == 8 -> unique banks
#define AS_ELE (128 * ASTR)
#define BS_ELE (16 * BSTR)

// Common prolog for all 128x128xK tile kernels (8 warps, warp = 32x64)
#define GEMM_PROLOG \
    __shared__ float As[2][AS_ELE]; \
    __shared__ float Bs[2][BS_ELE]; \
    int tid = threadIdx.x; int lane = tid & 31; int wid = tid >> 5; \
    int wm = (wid & 3) * 32, wn = (wid >> 2) * 64; \
    int g = lane >> 2, tg = lane & 3; \
    float acc[2][8][4] = {}; \
    uint32_t aBase = (uint32_t)__cvta_generic_to_shared(&As[0][0]); \
    uint32_t bBase = (uint32_t)__cvta_generic_to_shared(&Bs[0][0]); \
    int am = tid >> 2, ak = (tid & 3) * 4; \
    int bkr = tid >> 5, bnr = (tid & 31) * 4;

#define PREF(it, buf) do { int _k0 = (it) * 16; \
    cpa16(aBase + (uint32_t)((buf)*AS_ELE + am*ASTR + ak)*4,        rA0 + _k0 + ak, pa0); \
    cpa16(aBase + (uint32_t)((buf)*AS_ELE + (am+64)*ASTR + ak)*4,   rA1 + _k0 + ak, pa1); \
    cpa16(bBase + (uint32_t)((buf)*BS_ELE + bkr*BSTR + bnr)*4,      Bsrc + (size_t)(_k0+bkr)*ldb + bnr, true); \
    cpa16(bBase + (uint32_t)((buf)*BS_ELE + (bkr+8)*BSTR + bnr)*4,  Bsrc + (size_t)(_k0+bkr+8)*ldb + bnr, true); \
} while (0)

#define COMPUTE(cur) do { \
    const float* AsP = As[cur]; const float* BsP = Bs[cur]; \
    _Pragma("unroll") for (int kk = 0; kk < 2; ++kk) { \
        uint32_t afr[2][4]; \
        _Pragma("unroll") for (int mi = 0; mi < 2; ++mi) { \
            const float* ap = AsP + (wm + mi*16 + g)*ASTR + kk*8 + tg; \
            afr[mi][0] = f2b(ap[0]);        afr[mi][1] = f2b(ap[8*ASTR]); \
            afr[mi][2] = f2b(ap[4]);        afr[mi][3] = f2b(ap[8*ASTR + 4]); } \
        uint32_t bfr[8][2]; \
        _Pragma("unroll") for (int ni = 0; ni < 8; ++ni) { \
            const float* bp = BsP + (kk*8 + tg)*BSTR + wn + ni*8 + g; \
            bfr[ni][0] = f2b(bp[0]);        bfr[ni][1] = f2b(bp[4*BSTR]); } \
        _Pragma("unroll") for (int mi = 0; mi < 2; ++mi) \
        _Pragma("unroll") for (int ni = 0; ni < 8; ++ni) \
            mma8(acc[mi][ni], afr[mi], bfr[ni]); \
    } } while (0)

#define MAINLOOP(KITERS) \
    PREF(0, 0); CP_COMMIT; \
    for (int it = 0; it < (KITERS); ++it) { int cur = it & 1; \
        if (it + 1 < (KITERS)) PREF(it + 1, cur ^ 1); \
        CP_COMMIT; CP_WAIT1; __syncthreads(); \
        COMPUTE(cur); __syncthreads(); }

// ---------------------------------------------------------------------------
// Group samples by class
// ---------------------------------------------------------------------------
__global__ void group_kernel(const int* __restrict__ cls) {
    __shared__ int cnt[CCLS];
    __shared__ int off[CCLS + 1];
    int tid = threadIdx.x;
    if (tid < CCLS) cnt[tid] = 0;
    __syncthreads();
    for (int b = tid; b < BSZ; b += blockDim.x) atomicAdd(&cnt[cls[b]], 1);
    __syncthreads();
    if (tid == 0) {
        int s = 0;
        for (int c = 0; c < CCLS; c++) { off[c] = s; s += cnt[c]; }
        off[CCLS] = s;
        for (int c = 0; c <= CCLS; c++) g_class_off[c] = off[c];
    }
    __syncthreads();
    if (tid < CCLS) cnt[tid] = off[tid];
    __syncthreads();
    for (int b = tid; b < BSZ; b += blockDim.x) {
        int c = cls[b];
        int slot = atomicAdd(&cnt[c], 1);
        g_order[slot] = b;
    }
}

// ---------------------------------------------------------------------------
// colmean[c][d] = (1/cnt_c) * sum_n Xbuf[c][n][d]   (exact fp32 mean term)
// ---------------------------------------------------------------------------
__global__ __launch_bounds__(NT) void k_colmean(const float* __restrict__ Xbuf) {
    int c = blockIdx.y;
    int dl = threadIdx.x & 63;
    int d = blockIdx.x * 64 + dl;
    int stripe = threadIdx.x >> 6;
    int cnt = c_counts[c];
    const float* X = Xbuf + (size_t)c * NMAXX * DD + d;
    float s = 0.f;
#pragma unroll 4
    for (int n = stripe; n < cnt; n += 4) s += X[(size_t)n * DD];
    __shared__ float red[NT];
    red[threadIdx.x] = s;
    __syncthreads();
    if (stripe == 0) {
        float tot = red[dl] + red[dl + 64] + red[dl + 128] + red[dl + 192];
        g_colmean[c * DD + d] = tot / (float)cnt;
    }
}

// ---------------------------------------------------------------------------
// Kernel 1: h = gelu(z @ W1[:128] + W1[128+cid] + b1)   M=2048 K=128 N=1024
// ---------------------------------------------------------------------------
__global__ __launch_bounds__(NT, 2) void k_gemm_h(
    const float* __restrict__ z, const int* __restrict__ cls,
    const float* __restrict__ W1, const float* __restrict__ b1) {
    int m0 = blockIdx.y * 128, n0 = blockIdx.x * 128;
    GEMM_PROLOG
    const float* rA0 = z + (size_t)(m0 + am) * LATENT;
    const float* rA1 = z + (size_t)(m0 + am + 64) * LATENT;
    bool pa0 = true, pa1 = true;
    const float* Bsrc = W1 + n0; int ldb = HID;
    MAINLOOP(8)
#pragma unroll
    for (int mi = 0; mi < 2; ++mi)
#pragma unroll
    for (int r2 = 0; r2 < 2; ++r2) {
        int m = m0 + wm + mi * 16 + g + r2 * 8;
        int cid = cls[m];
        const float* wrow = W1 + (size_t)(LATENT + cid) * HID;
#pragma unroll
        for (int ni = 0; ni < 8; ++ni) {
            int n = n0 + wn + ni * 8 + tg * 2;
            float2 o;
            o.x = gelu_exact(acc[mi][ni][r2 * 2 + 0] + wrow[n] + b1[n]);
            o.y = gelu_exact(acc[mi][ni][r2 * 2 + 1] + wrow[n + 1] + b1[n + 1]);
            *(float2*)(g_h + (size_t)m * HID + n) = o;
        }
    }
}

// ---------------------------------------------------------------------------
// Kernel 2: t = gelu(h @ W2 + b2)    M=2048 K=1024 N=1024
// ---------------------------------------------------------------------------
__global__ __launch_bounds__(NT, 2) void k_gemm_t(
    const float* __restrict__ W2, const float* __restrict__ b2) {
    int m0 = blockIdx.y * 128, n0 = blockIdx.x * 128;
    GEMM_PROLOG
    const float* rA0 = g_h + (size_t)(m0 + am) * HID;
    const float* rA1 = g_h + (size_t)(m0 + am + 64) * HID;
    bool pa0 = true, pa1 = true;
    const float* Bsrc = W2 + n0; int ldb = HID;
    MAINLOOP(64)
#pragma unroll
    for (int mi = 0; mi < 2; ++mi)
#pragma unroll
    for (int r2 = 0; r2 < 2; ++r2) {
        int m = m0 + wm + mi * 16 + g + r2 * 8;
#pragma unroll
        for (int ni = 0; ni < 8; ++ni) {
            int n = n0 + wn + ni * 8 + tg * 2;
            float2 o;
            o.x = gelu_exact(acc[mi][ni][r2 * 2 + 0] + b2[n]);
            o.y = gelu_exact(acc[mi][ni][r2 * 2 + 1] + b2[n + 1]);
            *(float2*)(g_t + (size_t)m * HID + n) = o;
        }
    }
}

// ---------------------------------------------------------------------------
// Kernel 3: grouped logits: logits[r,n] = t[order[r]] . Wa[c][:,n] + ba
// ---------------------------------------------------------------------------
__global__ __launch_bounds__(NT, 2) void k_logits(
    const float* __restrict__ Wa, const float* __restrict__ ba) {
    int c = blockIdx.z;
    int off = g_class_off[c];
    int Bc = g_class_off[c + 1] - off;
    int mt = blockIdx.y, nt = blockIdx.x;
    if (mt * 128 >= Bc) return;
    int cnt = c_counts[c];
    if (nt * 128 >= cnt) return;
    int m0 = mt * 128, n0 = nt * 128;
    GEMM_PROLOG
    bool pa0 = (m0 + am) < Bc, pa1 = (m0 + am + 64) < Bc;
    const float* rA0 = pa0 ? g_t + (size_t)g_order[off + m0 + am] * HID : g_t;
    const float* rA1 = pa1 ? g_t + (size_t)g_order[off + m0 + am + 64] * HID : g_t;
    const float* Bsrc = Wa + (size_t)c * HID * NMAXX + n0; int ldb = NMAXX;
    MAINLOOP(64)
    const float* baC = ba + (size_t)c * NMAXX;
#pragma unroll
    for (int mi = 0; mi < 2; ++mi)
#pragma unroll
    for (int r2 = 0; r2 < 2; ++r2) {
        int ml = m0 + wm + mi * 16 + g + r2 * 8;
        if (ml < Bc) {
            size_t row = (size_t)(off + ml) * NMAXX;
#pragma unroll
            for (int ni = 0; ni < 8; ++ni) {
                int n = n0 + wn + ni * 8 + tg * 2;
                float2 bb = *(const float2*)(baC + n);
                float2 o;
                o.x = acc[mi][ni][r2 * 2 + 0] + bb.x;
                o.y = acc[mi][ni][r2 * 2 + 1] + bb.y;
                *(float2*)(g_logits + row + n) = o;
            }
        }
    }
}

// ---------------------------------------------------------------------------
// Kernel 4: softmax over valid prefix; writes beta = alpha - 1/cnt in place
// ---------------------------------------------------------------------------
__global__ __launch_bounds__(NT) void k_softmax() {
    int r = blockIdx.x;
    int c = 0;
#pragma unroll
    for (int i = 1; i < CCLS; i++)
        if (r >= g_class_off[i]) c = i;
    int cnt = c_counts[c];
    float* row = g_logits + (size_t)r * NMAXX;
    int tid = threadIdx.x;
    __shared__ float red[NT];

    float mx = -1e30f;
    for (int i = tid * 4; i < cnt; i += NT * 4) {
        float4 v = *(const float4*)(row + i);
        mx = fmaxf(mx, fmaxf(fmaxf(v.x, v.y), fmaxf(v.z, v.w)));
    }
    red[tid] = mx;
    __syncthreads();
    for (int s = NT / 2; s > 0; s >>= 1) {
        if (tid < s) red[tid] = fmaxf(red[tid], red[tid + s]);
        __syncthreads();
    }
    mx = red[0];
    __syncthreads();

    float sum = 0.f;
    for (int i = tid * 4; i < cnt; i += NT * 4) {
        float4 v = *(const float4*)(row + i);
        v.x = __expf(v.x - mx); v.y = __expf(v.y - mx);
        v.z = __expf(v.z - mx); v.w = __expf(v.w - mx);
        sum += v.x + v.y + v.z + v.w;
        *(float4*)(row + i) = v;
    }
    red[tid] = sum;
    __syncthreads();
    for (int s = NT / 2; s > 0; s >>= 1) {
        if (tid < s) red[tid] += red[tid + s];
        __syncthreads();
    }
    float inv = 1.0f / red[0];
    float invc = 1.0f / (float)cnt;
    __syncthreads();

    for (int i = tid * 4; i < cnt; i += NT * 4) {
        float4 v = *(const float4*)(row + i);
        v.x = v.x * inv - invc; v.y = v.y * inv - invc;
        v.z = v.z * inv - invc; v.w = v.w * inv - invc;
        *(float4*)(row + i) = v;
    }
}

// ---------------------------------------------------------------------------
// Kernel 5: out[order[r]] = colmean[c] + beta[r,:cnt] @ Xbuf[c][:cnt]
// ---------------------------------------------------------------------------
__global__ __launch_bounds__(NT, 2) void k_out(
    const float* __restrict__ Xbuf, float* __restrict__ out) {
    int c = blockIdx.z;
    int off = g_class_off[c];
    int Bc = g_class_off[c + 1] - off;
    int mt = blockIdx.y, nt = blockIdx.x;
    if (mt * 128 >= Bc) return;
    int cnt = c_counts[c];
    int m0 = mt * 128, n0 = nt * 128;
    GEMM_PROLOG
    bool pa0 = (m0 + am) < Bc, pa1 = (m0 + am + 64) < Bc;
    const float* rA0 = pa0 ? g_logits + (size_t)(off + m0 + am) * NMAXX : g_logits;
    const float* rA1 = pa1 ? g_logits + (size_t)(off + m0 + am + 64) * NMAXX : g_logits;
    const float* Bsrc = Xbuf + (size_t)c * NMAXX * DD + n0; int ldb = DD;
    int kit = cnt / 16;
    MAINLOOP(kit)
    const float* cm = g_colmean + c * DD;
#pragma unroll
    for (int mi = 0; mi < 2; ++mi)
#pragma unroll
    for (int r2 = 0; r2 < 2; ++r2) {
        int ml = m0 + wm + mi * 16 + g + r2 * 8;
        if (ml < Bc) {
            int b = g_order[off + ml];
#pragma unroll
            for (int ni = 0; ni < 8; ++ni) {
                int n = n0 + wn + ni * 8 + tg * 2;
                float2 m2 = *(const float2*)(cm + n);
                float2 o;
                o.x = acc[mi][ni][r2 * 2 + 0] + m2.x;
                o.y = acc[mi][ni][r2 * 2 + 1] + m2.y;
                *(float2*)(out + (size_t)b * DD + n) = o;
            }
        }
    }
}

// ---------------------------------------------------------------------------
extern "C" void kernel_launch(void* const* d_in, const int* in_sizes, int n_in,
                              void* d_out, int out_size) {
    const float* z   = (const float*)d_in[0];
    const int*   cls = (const int*)d_in[1];
    const float* W1  = (const float*)d_in[2];
    const float* b1  = (const float*)d_in[3];
    const float* W2  = (const float*)d_in[4];
    const float* b2  = (const float*)d_in[5];
    const float* Wa  = (const float*)d_in[6];
    const float* ba  = (const float*)d_in[7];
    const float* Xb  = (const float*)d_in[8];
    float* out = (float*)d_out;

    group_kernel<<<1, NT>>>(cls);
    k_colmean<<<dim3(DD / 64, CCLS), NT>>>(Xb);
    k_gemm_h<<<dim3(HID / 128, BSZ / 128), NT>>>(z, cls, W1, b1);
    k_gemm_t<<<dim3(HID / 128, BSZ / 128), NT>>>(W2, b2);
    k_logits<<<dim3(NMAXX / 128, BSZ / 128, CCLS), NT>>>(Wa, ba);
    k_softmax<<<BSZ, NT>>>();
    k_out<<<dim3(DD / 128, BSZ / 128, CCLS), NT>>>(Xb, out);
}

// round 3
// speedup vs baseline: 3.3532x; 1.1490x over previous
#include <cuda_runtime.h>
#include <math.h>
#include <stdint.h>

#define BSZ    2048
#define LATENT 128
#define CCLS   8
#define HID    1024
#define DD     512
#define NMAXX  4096
#define NT     256

__constant__ int c_counts[CCLS] = {1024, 1536, 2048, 2560, 3072, 3584, 3840, 4096};

// Scratch (device globals: allocation-free per harness rules)
__device__ __align__(16) float g_h[BSZ * HID];
__device__ __align__(16) float g_t[BSZ * HID];
__device__ __align__(16) float g_logits[(size_t)BSZ * NMAXX];
__device__ __align__(16) float g_colmean[CCLS * DD];
__device__ int g_order[BSZ];
__device__ int g_class_off[CCLS + 1];

__device__ __forceinline__ float gelu_exact(float x) {
    return 0.5f * x * (1.0f + erff(x * 0.70710678118654752f));
}
__device__ __forceinline__ uint32_t f2b(float f) { return __float_as_uint(f); }

// tf32 mma: D(16x8) += A(16x8) * B(8x8), fp32 accumulate
__device__ __forceinline__ void mma8(float* d, const uint32_t* a, const uint32_t* b) {
    asm volatile(
        "mma.sync.aligned.m16n8k8.row.col.f32.tf32.tf32.f32 "
        "{%0,%1,%2,%3},{%4,%5,%6,%7},{%8,%9},{%0,%1,%2,%3};\n"
        : "+f"(d[0]), "+f"(d[1]), "+f"(d[2]), "+f"(d[3])
        : "r"(a[0]), "r"(a[1]), "r"(a[2]), "r"(a[3]), "r"(b[0]), "r"(b[1]));
}

__device__ __forceinline__ void cpa16(uint32_t dst, const float* src, bool pred) {
    int sz = pred ? 16 : 0;  // sz=0 -> zero-fill (deterministic)
    asm volatile("cp.async.ca.shared.global [%0], [%1], 16, %2;\n"
                 :: "r"(dst), "l"(src), "r"(sz));
}
#define CP_COMMIT asm volatile("cp.async.commit_group;\n")
#define CP_WAIT1  asm volatile("cp.async.wait_group 1;\n")

// Tile: M=64, N=128, K-step=16, 3-stage pipeline, 256 threads (8 warps 2x4)
#define STAGES 3
#define ASTR 20     // A smem row stride (words): conflict-free fragment loads
#define BSTR 136    // B smem row stride (words): 136 % 32 == 8 -> unique banks
#define AS_ELE (64 * ASTR)
#define BS_ELE (16 * BSTR)

#define GEMM_PROLOG \
    __shared__ float As[STAGES][AS_ELE]; \
    __shared__ float Bs[STAGES][BS_ELE]; \
    int tid = threadIdx.x; int lane = tid & 31; int wid = tid >> 5; \
    int wm = (wid & 1) * 32, wn = (wid >> 1) * 32; \
    int g = lane >> 2, tg = lane & 3; \
    float acc[2][4][4] = {}; \
    uint32_t aBase = (uint32_t)__cvta_generic_to_shared(&As[0][0]); \
    uint32_t bBase = (uint32_t)__cvta_generic_to_shared(&Bs[0][0]); \
    int am = tid >> 2, ak = (tid & 3) * 4; \
    int bkr = tid >> 5, bnr = (tid & 31) * 4;

#define PREF(it, buf) do { int _k0 = (it) * 16; \
    cpa16(aBase + (uint32_t)((buf)*AS_ELE + am*ASTR + ak)*4,       rA0 + _k0 + ak, pa0); \
    cpa16(bBase + (uint32_t)((buf)*BS_ELE + bkr*BSTR + bnr)*4,     Bsrc + (size_t)(_k0+bkr)*ldb + bnr, true); \
    cpa16(bBase + (uint32_t)((buf)*BS_ELE + (bkr+8)*BSTR + bnr)*4, Bsrc + (size_t)(_k0+bkr+8)*ldb + bnr, true); \
} while (0)

#define COMPUTE(cur) do { \
    const float* AsP = As[cur]; const float* BsP = Bs[cur]; \
    _Pragma("unroll") for (int kk = 0; kk < 2; ++kk) { \
        uint32_t afr[2][4]; \
        _Pragma("unroll") for (int mi = 0; mi < 2; ++mi) { \
            const float* ap = AsP + (wm + mi*16 + g)*ASTR + kk*8 + tg; \
            afr[mi][0] = f2b(ap[0]);  afr[mi][1] = f2b(ap[8*ASTR]); \
            afr[mi][2] = f2b(ap[4]);  afr[mi][3] = f2b(ap[8*ASTR + 4]); } \
        uint32_t bfr[4][2]; \
        _Pragma("unroll") for (int ni = 0; ni < 4; ++ni) { \
            const float* bp = BsP + (kk*8 + tg)*BSTR + wn + ni*8 + g; \
            bfr[ni][0] = f2b(bp[0]);  bfr[ni][1] = f2b(bp[4*BSTR]); } \
        _Pragma("unroll") for (int mi = 0; mi < 2; ++mi) \
        _Pragma("unroll") for (int ni = 0; ni < 4; ++ni) \
            mma8(acc[mi][ni], afr[mi], bfr[ni]); \
    } } while (0)

// One __syncthreads per iter: wait -> sync -> prefetch freed buffer -> compute
#define MAINLOOP(KITERS) \
    PREF(0, 0); CP_COMMIT; \
    PREF(1, 1); CP_COMMIT; \
    for (int it = 0; it < (KITERS); ++it) { \
        int cur = it % STAGES; \
        CP_WAIT1; \
        __syncthreads(); \
        int nx = it + STAGES - 1; \
        if (nx < (KITERS)) { PREF(nx, nx % STAGES); } \
        CP_COMMIT; \
        COMPUTE(cur); \
    }

// ---------------------------------------------------------------------------
// Group samples by class
// ---------------------------------------------------------------------------
__global__ void group_kernel(const int* __restrict__ cls) {
    __shared__ int cnt[CCLS];
    __shared__ int off[CCLS + 1];
    int tid = threadIdx.x;
    if (tid < CCLS) cnt[tid] = 0;
    __syncthreads();
    for (int b = tid; b < BSZ; b += blockDim.x) atomicAdd(&cnt[cls[b]], 1);
    __syncthreads();
    if (tid == 0) {
        int s = 0;
        for (int c = 0; c < CCLS; c++) { off[c] = s; s += cnt[c]; }
        off[CCLS] = s;
        for (int c = 0; c <= CCLS; c++) g_class_off[c] = off[c];
    }
    __syncthreads();
    if (tid < CCLS) cnt[tid] = off[tid];
    __syncthreads();
    for (int b = tid; b < BSZ; b += blockDim.x) {
        int c = cls[b];
        int slot = atomicAdd(&cnt[c], 1);
        g_order[slot] = b;
    }
}

// ---------------------------------------------------------------------------
// colmean[c][d] = (1/cnt_c) * sum_n Xbuf[c][n][d]
// ---------------------------------------------------------------------------
__global__ __launch_bounds__(NT) void k_colmean(const float* __restrict__ Xbuf) {
    int c = blockIdx.y;
    int dl = threadIdx.x & 63;
    int d = blockIdx.x * 64 + dl;
    int stripe = threadIdx.x >> 6;
    int cnt = c_counts[c];
    const float* X = Xbuf + (size_t)c * NMAXX * DD + d;
    float s = 0.f;
#pragma unroll 4
    for (int n = stripe; n < cnt; n += 4) s += X[(size_t)n * DD];
    __shared__ float red[NT];
    red[threadIdx.x] = s;
    __syncthreads();
    if (stripe == 0) {
        float tot = red[dl] + red[dl + 64] + red[dl + 128] + red[dl + 192];
        g_colmean[c * DD + d] = tot / (float)cnt;
    }
}

// ---------------------------------------------------------------------------
// Kernel 1: h = gelu(z @ W1[:128] + W1[128+cid] + b1)   M=2048 K=128 N=1024
// ---------------------------------------------------------------------------
__global__ __launch_bounds__(NT, 2) void k_gemm_h(
    const float* __restrict__ z, const int* __restrict__ cls,
    const float* __restrict__ W1, const float* __restrict__ b1) {
    int m0 = blockIdx.y * 64, n0 = blockIdx.x * 128;
    GEMM_PROLOG
    const float* rA0 = z + (size_t)(m0 + am) * LATENT;
    bool pa0 = true;
    const float* Bsrc = W1 + n0; int ldb = HID;
    MAINLOOP(8)
#pragma unroll
    for (int mi = 0; mi < 2; ++mi)
#pragma unroll
    for (int r2 = 0; r2 < 2; ++r2) {
        int m = m0 + wm + mi * 16 + g + r2 * 8;
        int cid = cls[m];
        const float* wrow = W1 + (size_t)(LATENT + cid) * HID;
#pragma unroll
        for (int ni = 0; ni < 4; ++ni) {
            int n = n0 + wn + ni * 8 + tg * 2;
            float2 o;
            o.x = gelu_exact(acc[mi][ni][r2 * 2 + 0] + wrow[n] + b1[n]);
            o.y = gelu_exact(acc[mi][ni][r2 * 2 + 1] + wrow[n + 1] + b1[n + 1]);
            *(float2*)(g_h + (size_t)m * HID + n) = o;
        }
    }
}

// ---------------------------------------------------------------------------
// Kernel 2: t = gelu(h @ W2 + b2)    M=2048 K=1024 N=1024
// ---------------------------------------------------------------------------
__global__ __launch_bounds__(NT, 2) void k_gemm_t(
    const float* __restrict__ W2, const float* __restrict__ b2) {
    int m0 = blockIdx.y * 64, n0 = blockIdx.x * 128;
    GEMM_PROLOG
    const float* rA0 = g_h + (size_t)(m0 + am) * HID;
    bool pa0 = true;
    const float* Bsrc = W2 + n0; int ldb = HID;
    MAINLOOP(64)
#pragma unroll
    for (int mi = 0; mi < 2; ++mi)
#pragma unroll
    for (int r2 = 0; r2 < 2; ++r2) {
        int m = m0 + wm + mi * 16 + g + r2 * 8;
#pragma unroll
        for (int ni = 0; ni < 4; ++ni) {
            int n = n0 + wn + ni * 8 + tg * 2;
            float2 o;
            o.x = gelu_exact(acc[mi][ni][r2 * 2 + 0] + b2[n]);
            o.y = gelu_exact(acc[mi][ni][r2 * 2 + 1] + b2[n + 1]);
            *(float2*)(g_t + (size_t)m * HID + n) = o;
        }
    }
}

// ---------------------------------------------------------------------------
// Kernel 3: grouped logits: logits[r,n] = t[order[r]] . Wa[c][:,n] + ba
// ---------------------------------------------------------------------------
__global__ __launch_bounds__(NT, 2) void k_logits(
    const float* __restrict__ Wa, const float* __restrict__ ba) {
    int c = blockIdx.z;
    int off = g_class_off[c];
    int Bc = g_class_off[c + 1] - off;
    int mt = blockIdx.y, nt = blockIdx.x;
    if (mt * 64 >= Bc) return;
    int cnt = c_counts[c];
    if (nt * 128 >= cnt) return;
    int m0 = mt * 64, n0 = nt * 128;
    GEMM_PROLOG
    bool pa0 = (m0 + am) < Bc;
    const float* rA0 = pa0 ? g_t + (size_t)g_order[off + m0 + am] * HID : g_t;
    const float* Bsrc = Wa + (size_t)c * HID * NMAXX + n0; int ldb = NMAXX;
    MAINLOOP(64)
    const float* baC = ba + (size_t)c * NMAXX;
#pragma unroll
    for (int mi = 0; mi < 2; ++mi)
#pragma unroll
    for (int r2 = 0; r2 < 2; ++r2) {
        int ml = m0 + wm + mi * 16 + g + r2 * 8;
        if (ml < Bc) {
            size_t row = (size_t)(off + ml) * NMAXX;
#pragma unroll
            for (int ni = 0; ni < 4; ++ni) {
                int n = n0 + wn + ni * 8 + tg * 2;
                float2 bb = *(const float2*)(baC + n);
                float2 o;
                o.x = acc[mi][ni][r2 * 2 + 0] + bb.x;
                o.y = acc[mi][ni][r2 * 2 + 1] + bb.y;
                *(float2*)(g_logits + row + n) = o;
            }
        }
    }
}

// ---------------------------------------------------------------------------
// Kernel 4: softmax over valid prefix; writes beta = alpha - 1/cnt in place
// ---------------------------------------------------------------------------
__global__ __launch_bounds__(NT) void k_softmax() {
    int r = blockIdx.x;
    int c = 0;
#pragma unroll
    for (int i = 1; i < CCLS; i++)
        if (r >= g_class_off[i]) c = i;
    int cnt = c_counts[c];
    float* row = g_logits + (size_t)r * NMAXX;
    int tid = threadIdx.x;
    __shared__ float red[NT];

    float mx = -1e30f;
    for (int i = tid * 4; i < cnt; i += NT * 4) {
        float4 v = *(const float4*)(row + i);
        mx = fmaxf(mx, fmaxf(fmaxf(v.x, v.y), fmaxf(v.z, v.w)));
    }
    red[tid] = mx;
    __syncthreads();
    for (int s = NT / 2; s > 0; s >>= 1) {
        if (tid < s) red[tid] = fmaxf(red[tid], red[tid + s]);
        __syncthreads();
    }
    mx = red[0];
    __syncthreads();

    float sum = 0.f;
    for (int i = tid * 4; i < cnt; i += NT * 4) {
        float4 v = *(const float4*)(row + i);
        v.x = __expf(v.x - mx); v.y = __expf(v.y - mx);
        v.z = __expf(v.z - mx); v.w = __expf(v.w - mx);
        sum += v.x + v.y + v.z + v.w;
        *(float4*)(row + i) = v;
    }
    red[tid] = sum;
    __syncthreads();
    for (int s = NT / 2; s > 0; s >>= 1) {
        if (tid < s) red[tid] += red[tid + s];
        __syncthreads();
    }
    float inv = 1.0f / red[0];
    float invc = 1.0f / (float)cnt;
    __syncthreads();

    for (int i = tid * 4; i < cnt; i += NT * 4) {
        float4 v = *(const float4*)(row + i);
        v.x = v.x * inv - invc; v.y = v.y * inv - invc;
        v.z = v.z * inv - invc; v.w = v.w * inv - invc;
        *(float4*)(row + i) = v;
    }
}

// ---------------------------------------------------------------------------
// Kernel 5: out[order[r]] = colmean[c] + beta[r,:cnt] @ Xbuf[c][:cnt]
// ---------------------------------------------------------------------------
__global__ __launch_bounds__(NT, 2) void k_out(
    const float* __restrict__ Xbuf, float* __restrict__ out) {
    int c = blockIdx.z;
    int off = g_class_off[c];
    int Bc = g_class_off[c + 1] - off;
    int mt = blockIdx.y, nt = blockIdx.x;
    if (mt * 64 >= Bc) return;
    int cnt = c_counts[c];
    int m0 = mt * 64, n0 = nt * 128;
    GEMM_PROLOG
    bool pa0 = (m0 + am) < Bc;
    const float* rA0 = pa0 ? g_logits + (size_t)(off + m0 + am) * NMAXX : g_logits;
    const float* Bsrc = Xbuf + (size_t)c * NMAXX * DD + n0; int ldb = DD;
    int kit = cnt / 16;
    MAINLOOP(kit)
    const float* cm = g_colmean + c * DD;
#pragma unroll
    for (int mi = 0; mi < 2; ++mi)
#pragma unroll
    for (int r2 = 0; r2 < 2; ++r2) {
        int ml = m0 + wm + mi * 16 + g + r2 * 8;
        if (ml < Bc) {
            int b = g_order[off + ml];
#pragma unroll
            for (int ni = 0; ni < 4; ++ni) {
                int n = n0 + wn + ni * 8 + tg * 2;
                float2 m2 = *(const float2*)(cm + n);
                float2 o;
                o.x = acc[mi][ni][r2 * 2 + 0] + m2.x;
                o.y = acc[mi][ni][r2 * 2 + 1] + m2.y;
                *(float2*)(out + (size_t)b * DD + n) = o;
            }
        }
    }
}

// ---------------------------------------------------------------------------
extern "C" void kernel_launch(void* const* d_in, const int* in_sizes, int n_in,
                              void* d_out, int out_size) {
    const float* z   = (const float*)d_in[0];
    const int*   cls = (const int*)d_in[1];
    const float* W1  = (const float*)d_in[2];
    const float* b1  = (const float*)d_in[3];
    const float* W2  = (const float*)d_in[4];
    const float* b2  = (const float*)d_in[5];
    const float* Wa  = (const float*)d_in[6];
    const float* ba  = (const float*)d_in[7];
    const float* Xb  = (const float*)d_in[8];
    float* out = (float*)d_out;

    group_kernel<<<1, NT>>>(cls);
    k_colmean<<<dim3(DD / 64, CCLS), NT>>>(Xb);
    k_gemm_h<<<dim3(HID / 128, BSZ / 64), NT>>>(z, cls, W1, b1);
    k_gemm_t<<<dim3(HID / 128, BSZ / 64), NT>>>(W2, b2);
    k_logits<<<dim3(NMAXX / 128, BSZ / 64, CCLS), NT>>>(Wa, ba);
    k_softmax<<<BSZ, NT>>>();
    k_out<<<dim3(DD / 128, BSZ / 64, CCLS), NT>>>(Xb, out);
}